// round 13
// baseline (speedup 1.0000x reference)
#include <cuda_runtime.h>

// B=32, P=3, D=300, N=2048.  x,y: [B,P,D,N] fp32.
// out: [B, P*N, 3] = {cos, l2, l1} per (b,p,n) vector of length D (stride N).
//
// R12 champion (float4/thread, 1536x32, forced ping-pong) deepened CH 6->10:
// 40 LDG.128 in flight/thread (~208KB/SM, under M_max=55/warp). regs ~200
// at 1 warp/block (255 ceiling). Fourth notch on the in-flight-depth axis
// (R10 80.2% -> R11 82.0% -> R12 85.5% DRAM, all as predicted).

#define D_DIM 300
#define CH 10                 // d-rows per chunk
#define NCHUNK (D_DIM / CH)   // 30
#define N_DIM 2048
#define N4 (N_DIM / 4)        // 512
#define BP 96
#define THREADS 32

__device__ __forceinline__ float4 ldg4_nc(const float4* p)
{
    float4 v;
    asm("ld.global.nc.L2::256B.v4.f32 {%0, %1, %2, %3}, [%4];"
        : "=f"(v.x), "=f"(v.y), "=f"(v.z), "=f"(v.w) : "l"(p));
    return v;
}

#define LOAD_CHUNK(A_, B_, base)                                    \
    do {                                                            \
        const size_t _o = (size_t)(base) * N4;                      \
        _Pragma("unroll")                                           \
        for (int _i = 0; _i < CH; ++_i) {                           \
            A_[_i] = ldg4_nc(xp + _o + (size_t)_i * N4);            \
            B_[_i] = ldg4_nc(yp + _o + (size_t)_i * N4);            \
        }                                                           \
    } while (0)

#define COMPUTE_CHUNK(A_, B_)                                       \
    do {                                                            \
        _Pragma("unroll")                                           \
        for (int _i = 0; _i < CH; ++_i) {                           \
            const float _ax[4] = {A_[_i].x, A_[_i].y, A_[_i].z, A_[_i].w}; \
            const float _bx[4] = {B_[_i].x, B_[_i].y, B_[_i].z, B_[_i].w}; \
            _Pragma("unroll")                                       \
            for (int _j = 0; _j < 4; ++_j) {                        \
                const float _a = _ax[_j], _b = _bx[_j];             \
                dot[_j] = fmaf(_a, _b, dot[_j]);                    \
                xx [_j] = fmaf(_a, _a, xx [_j]);                    \
                yy [_j] = fmaf(_b, _b, yy [_j]);                    \
                const float _d = _a - _b;                           \
                dd [_j] = fmaf(_d, _d, dd [_j]);                    \
                l1 [_j] += fabsf(_d);                               \
            }                                                       \
        }                                                           \
    } while (0)

__global__ __launch_bounds__(THREADS)
void sim_measure_kernel(const float* __restrict__ x,
                        const float* __restrict__ y,
                        float* __restrict__ out)
{
    const int idx = blockIdx.x * THREADS + threadIdx.x;   // float4-column id
    const int n4 = idx & (N4 - 1);
    const int bp = idx >> 9;                              // / 512

    const float4* __restrict__ xp =
        reinterpret_cast<const float4*>(x) + (size_t)bp * D_DIM * N4 + n4;
    const float4* __restrict__ yp =
        reinterpret_cast<const float4*>(y) + (size_t)bp * D_DIM * N4 + n4;

    float dot[4] = {0.f, 0.f, 0.f, 0.f};
    float xx [4] = {0.f, 0.f, 0.f, 0.f};
    float yy [4] = {0.f, 0.f, 0.f, 0.f};
    float dd [4] = {0.f, 0.f, 0.f, 0.f};
    float l1 [4] = {0.f, 0.f, 0.f, 0.f};

    float4 a0[CH], b0[CH], a1[CH], b1[CH];

    LOAD_CHUNK(a0, b0, 0 * CH);
    LOAD_CHUNK(a1, b1, 1 * CH);

    // NCHUNK = 30 (even): loop (c = 0,2,..,26) computes chunks 0..27 and
    // loads 2..29; epilogue computes the pre-loaded 28, 29.
    #pragma unroll 1
    for (int c = 0; c + 3 < NCHUNK; c += 2) {
        COMPUTE_CHUNK(a0, b0);
        LOAD_CHUNK(a0, b0, (c + 2) * CH);
        COMPUTE_CHUNK(a1, b1);
        LOAD_CHUNK(a1, b1, (c + 3) * CH);
    }
    COMPUTE_CHUNK(a0, b0);   // chunk 28
    COMPUTE_CHUNK(a1, b1);   // chunk 29

    // out layout: [bp, n, 3], 4 consecutive n per thread
    const int n0 = n4 * 4;
    float* o = out + ((size_t)bp * N_DIM + n0) * 3;
    #pragma unroll
    for (int j = 0; j < 4; ++j) {
        o[j * 3 + 0] = dot[j] * rsqrtf(xx[j] * yy[j]);
        o[j * 3 + 1] = sqrtf(dd[j]);
        o[j * 3 + 2] = l1[j];
    }
}

extern "C" void kernel_launch(void* const* d_in, const int* in_sizes, int n_in,
                              void* d_out, int out_size)
{
    const float* x = (const float*)d_in[0];
    const float* y = (const float*)d_in[1];
    float* out = (float*)d_out;

    const int total_threads = BP * N4;           // 49152
    const int blocks = total_threads / THREADS;  // 1536
    sim_measure_kernel<<<blocks, THREADS>>>(x, y, out);
}